// round 4
// baseline (speedup 1.0000x reference)
#include <cuda_runtime.h>

#define BB 8
#define NN 2048
#define FIN 256
#define FOUT 64
#define LALPHA 0.2f
#define EBIAS 16.0f
#define SPLIT 16

// ---- scratch (device globals; no allocation) ----
__device__ float g_WhL[BB * NN * FOUT];   // Wh * level  (4 MB)
__device__ float g_f1[BB * NN];
__device__ float g_f2[BB * NN];
__device__ float g_part[SPLIT * BB * NN];
__device__ float g_inv[BB * NN];

// =====================================================================
// Kernel A: Wh = h@W, WhL = Wh*level, f1 = Wh@a1, f2 = Wh@a2
// 512 blocks x 256 threads, 32 rows per block.
// =====================================================================
__global__ __launch_bounds__(256) void k_proj(const float* __restrict__ h,
                                              const float* __restrict__ W,
                                              const float* __restrict__ a,
                                              const float* __restrict__ level)
{
    __shared__ float sh_h[32 * FIN];      // 32 KB
    __shared__ float red1[8][4][2];
    __shared__ float red2[8][4][2];

    const int t = threadIdx.x;
    const int row0 = blockIdx.x * 32;

    // stage 32 h-rows (8192 floats) into smem
    const float4* hg = (const float4*)(h + (size_t)row0 * FIN);
    float4* hs = (float4*)sh_h;
#pragma unroll
    for (int k = 0; k < 8; ++k) hs[t + k * 256] = hg[t + k * 256];
    __syncthreads();

    const int o = t & 63;       // output feature
    const int g = t >> 6;       // row group (4 groups x 8 rows)
    const float a1o = a[o];
    const float a2o = a[FOUT + o];

    float acc[8] = {0.f, 0.f, 0.f, 0.f, 0.f, 0.f, 0.f, 0.f};

#pragma unroll 4
    for (int f4 = 0; f4 < FIN / 4; ++f4) {
        const float w0 = __ldg(&W[(f4 * 4 + 0) * FOUT + o]);
        const float w1 = __ldg(&W[(f4 * 4 + 1) * FOUT + o]);
        const float w2 = __ldg(&W[(f4 * 4 + 2) * FOUT + o]);
        const float w3 = __ldg(&W[(f4 * 4 + 3) * FOUT + o]);
#pragma unroll
        for (int rr = 0; rr < 8; ++rr) {
            const float4 hv = *(const float4*)&sh_h[(g * 8 + rr) * FIN + f4 * 4];
            acc[rr] = fmaf(hv.x, w0, acc[rr]);
            acc[rr] = fmaf(hv.y, w1, acc[rr]);
            acc[rr] = fmaf(hv.z, w2, acc[rr]);
            acc[rr] = fmaf(hv.w, w3, acc[rr]);
        }
    }

    const int lane = t & 31;
    const int half = (t >> 5) & 1;
#pragma unroll
    for (int rr = 0; rr < 8; ++rr) {
        const int row = row0 + g * 8 + rr;
        const float lev = __ldg(&level[row]);
        g_WhL[(size_t)row * FOUT + o] = acc[rr] * lev;
        float v1 = acc[rr] * a1o;
        float v2 = acc[rr] * a2o;
#pragma unroll
        for (int off = 16; off; off >>= 1) {
            v1 += __shfl_down_sync(0xffffffffu, v1, off);
            v2 += __shfl_down_sync(0xffffffffu, v2, off);
        }
        if (lane == 0) { red1[rr][g][half] = v1; red2[rr][g][half] = v2; }
    }
    __syncthreads();
    if (t < 32) {
        const int g2 = t >> 3, rr2 = t & 7;
        const int row = row0 + g2 * 8 + rr2;
        g_f1[row] = red1[rr2][g2][0] + red1[rr2][g2][1];
        g_f2[row] = red2[rr2][g2][0] + red2[rr2][g2][1];
    }
}

// =====================================================================
// Kernel B: partial column sums of exp(e - EBIAS) over i.
// grid (N/256, B, SPLIT); thread owns one column j -> coalesced rows.
// =====================================================================
__global__ __launch_bounds__(256) void k_colsum(const int* __restrict__ adj,
                                                const float* __restrict__ nt)
{
    const int j = blockIdx.x * 256 + threadIdx.x;
    const int b = blockIdx.y;
    const int i0 = blockIdx.z * (NN / SPLIT);

    const float f2j = __ldg(&g_f2[b * NN + j]);
    const float* f1p = g_f1 + b * NN + i0;
    size_t base = ((size_t)(b * NN + i0)) * NN + j;

    float s = 0.f;
#pragma unroll 4
    for (int ii = 0; ii < NN / SPLIT; ++ii) {
        const int av = __ldg(adj + base);
        const float ntv = __ldg(nt + base);
        const float f1i = __ldg(&f1p[ii]);
        base += NN;
        if (av > 0) {
            const float x = f1i + f2j;
            const float e = (x > 0.f ? x : LALPHA * x) * ntv;
            s += __expf(e - EBIAS);
        }
    }
    g_part[((size_t)blockIdx.z * BB + b) * NN + j] = s;
}

// =====================================================================
// Combine partials -> 1/colsum (deterministic tree, no atomics)
// =====================================================================
__global__ __launch_bounds__(256) void k_comb()
{
    const int c = blockIdx.x * 256 + threadIdx.x;
    float s = 0.f;
#pragma unroll
    for (int k = 0; k < SPLIT; ++k) s += g_part[k * (BB * NN) + c];
    g_inv[c] = 1.0f / s;
}

// =====================================================================
// Kernel C: out[b,i,o] = relu( sum_j P[b,i,j] * WhL[b,j,o] )
// P recomputed on the fly. 256 blocks, 64 i-rows x 64 o per block.
// Packed f32x2 FMAs (FFMA2) for 2x fp32 throughput.
// =====================================================================
__global__ __launch_bounds__(256) void k_attn(const int* __restrict__ adj,
                                              const float* __restrict__ nt,
                                              float* __restrict__ out)
{
    __shared__ float sh_w[64 * 64];   // WhL chunk [jj][o], 16 KB
    __shared__ float sh_p[64 * 65];   // P transposed [jj][il], padded
    __shared__ float sh_f1[64];

    const int t = threadIdx.x;
    const int b = blockIdx.x >> 5;             // 32 blocks per batch
    const int i0 = (blockIdx.x & 31) * 64;

    if (t < 64) sh_f1[t] = g_f1[b * NN + i0 + t];
    __syncthreads();

    // P-phase mapping
    const int jj = t & 63;
    const int ig = t >> 6;                     // 4 groups x 16 rows

    // matmul mapping: rows il and il+32, 8 outputs starting at oc
    const int il = t & 31;
    const int oc = (t >> 5) * 8;

    unsigned long long acc0[4] = {0ull, 0ull, 0ull, 0ull};
    unsigned long long acc1[4] = {0ull, 0ull, 0ull, 0ull};

    for (int j0 = 0; j0 < NN; j0 += 64) {
        // --- stage WhL chunk: 64x64 floats, contiguous ---
        {
            const float4* src = (const float4*)(g_WhL + ((size_t)(b * NN + j0)) * FOUT);
            float4* dst = (float4*)sh_w;
#pragma unroll
            for (int k = 0; k < 4; ++k) dst[t + k * 256] = src[t + k * 256];
        }

        // --- compute P for 64 rows x 64 cols ---
        {
            const float f2j  = __ldg(&g_f2[b * NN + j0 + jj]);
            const float invj = __ldg(&g_inv[b * NN + j0 + jj]);
            size_t base = ((size_t)(b * NN + i0 + ig * 16)) * NN + j0 + jj;
#pragma unroll 4
            for (int r = 0; r < 16; ++r) {
                const int av = __ldg(adj + base);
                const float ntv = __ldg(nt + base);
                base += NN;
                float pv = 0.f;
                if (av > 0) {
                    const float x = sh_f1[ig * 16 + r] + f2j;
                    const float e = (x > 0.f ? x : LALPHA * x) * ntv;
                    pv = __expf(e - EBIAS) * invj;
                }
                sh_p[jj * 65 + ig * 16 + r] = pv;
            }
        }
        __syncthreads();

        // --- accumulate: acc[i][o] += P[i][jj] * WhL[jj][o] ---
#pragma unroll 8
        for (int j = 0; j < 64; ++j) {
            const float p0 = sh_p[j * 65 + il];
            const float p1 = sh_p[j * 65 + il + 32];
            unsigned long long pp0, pp1;
            asm("mov.b64 %0, {%1, %1};" : "=l"(pp0) : "f"(p0));
            asm("mov.b64 %0, {%1, %1};" : "=l"(pp1) : "f"(p1));
            const ulonglong2* wv = (const ulonglong2*)&sh_w[j * 64 + oc];
            const ulonglong2 wA = wv[0];
            const ulonglong2 wB = wv[1];
            asm("fma.rn.f32x2 %0, %1, %2, %0;" : "+l"(acc0[0]) : "l"(pp0), "l"(wA.x));
            asm("fma.rn.f32x2 %0, %1, %2, %0;" : "+l"(acc0[1]) : "l"(pp0), "l"(wA.y));
            asm("fma.rn.f32x2 %0, %1, %2, %0;" : "+l"(acc0[2]) : "l"(pp0), "l"(wB.x));
            asm("fma.rn.f32x2 %0, %1, %2, %0;" : "+l"(acc0[3]) : "l"(pp0), "l"(wB.y));
            asm("fma.rn.f32x2 %0, %1, %2, %0;" : "+l"(acc1[0]) : "l"(pp1), "l"(wA.x));
            asm("fma.rn.f32x2 %0, %1, %2, %0;" : "+l"(acc1[1]) : "l"(pp1), "l"(wA.y));
            asm("fma.rn.f32x2 %0, %1, %2, %0;" : "+l"(acc1[2]) : "l"(pp1), "l"(wB.x));
            asm("fma.rn.f32x2 %0, %1, %2, %0;" : "+l"(acc1[3]) : "l"(pp1), "l"(wB.y));
        }
        __syncthreads();
    }

    // --- epilogue: relu + store ---
    float r0[8], r1[8];
#pragma unroll
    for (int k = 0; k < 4; ++k) {
        float lo, hi;
        asm("mov.b64 {%0, %1}, %2;" : "=f"(lo), "=f"(hi) : "l"(acc0[k]));
        r0[2 * k] = fmaxf(lo, 0.f); r0[2 * k + 1] = fmaxf(hi, 0.f);
        asm("mov.b64 {%0, %1}, %2;" : "=f"(lo), "=f"(hi) : "l"(acc1[k]));
        r1[2 * k] = fmaxf(lo, 0.f); r1[2 * k + 1] = fmaxf(hi, 0.f);
    }
    float* op0 = out + ((size_t)(b * NN + i0 + il)) * FOUT + oc;
    float* op1 = out + ((size_t)(b * NN + i0 + il + 32)) * FOUT + oc;
    ((float4*)op0)[0] = make_float4(r0[0], r0[1], r0[2], r0[3]);
    ((float4*)op0)[1] = make_float4(r0[4], r0[5], r0[6], r0[7]);
    ((float4*)op1)[0] = make_float4(r1[0], r1[1], r1[2], r1[3]);
    ((float4*)op1)[1] = make_float4(r1[4], r1[5], r1[6], r1[7]);
}

// =====================================================================
extern "C" void kernel_launch(void* const* d_in, const int* in_sizes, int n_in,
                              void* d_out, int out_size)
{
    const float* h     = (const float*)d_in[0];
    const int*   adj   = (const int*)  d_in[1];
    const float* level = (const float*)d_in[2];
    const float* nt    = (const float*)d_in[3];
    const float* W     = (const float*)d_in[4];
    const float* a     = (const float*)d_in[5];
    float* out = (float*)d_out;

    k_proj<<<(BB * NN) / 32, 256>>>(h, W, a, level);
    dim3 gb(NN / 256, BB, SPLIT);
    k_colsum<<<gb, 256>>>(adj, nt);
    k_comb<<<(BB * NN) / 256, 256>>>();
    k_attn<<<(BB * NN) / 64, 256>>>(adj, nt, out);
}

// round 5
// speedup vs baseline: 1.4474x; 1.4474x over previous
#include <cuda_runtime.h>

#define BB 8
#define NN 2048
#define FIN 256
#define FOUT 64
#define LALPHA 0.2f
#define EBIAS 16.0f
#define SPLIT 16
#define SPLITJ 4

// ---- scratch (device globals; no allocation) ----
__device__ float g_WhL[BB * NN * FOUT];            // Wh*level, later *inv  (4 MB)
__device__ float g_f1[BB * NN];
__device__ float g_f2[BB * NN];
__device__ float g_part[SPLIT * BB * NN];
__device__ float g_inv[BB * NN];
__device__ float g_expe[(size_t)BB * NN * NN];     // exp(e-16), masked->0 (134 MB)
__device__ float g_pout[(size_t)SPLITJ * BB * NN * FOUT];  // j-split partials (16 MB)

// =====================================================================
// Kernel A: Wh = h@W, WhL = Wh*level, f1 = Wh@a1, f2 = Wh@a2
// =====================================================================
__global__ __launch_bounds__(256) void k_proj(const float* __restrict__ h,
                                              const float* __restrict__ W,
                                              const float* __restrict__ a,
                                              const float* __restrict__ level)
{
    __shared__ float sh_h[32 * FIN];
    __shared__ float red1[8][4][2];
    __shared__ float red2[8][4][2];

    const int t = threadIdx.x;
    const int row0 = blockIdx.x * 32;

    const float4* hg = (const float4*)(h + (size_t)row0 * FIN);
    float4* hs = (float4*)sh_h;
#pragma unroll
    for (int k = 0; k < 8; ++k) hs[t + k * 256] = hg[t + k * 256];
    __syncthreads();

    const int o = t & 63;
    const int g = t >> 6;
    const float a1o = a[o];
    const float a2o = a[FOUT + o];

    float acc[8] = {0.f, 0.f, 0.f, 0.f, 0.f, 0.f, 0.f, 0.f};

#pragma unroll 4
    for (int f4 = 0; f4 < FIN / 4; ++f4) {
        const float w0 = __ldg(&W[(f4 * 4 + 0) * FOUT + o]);
        const float w1 = __ldg(&W[(f4 * 4 + 1) * FOUT + o]);
        const float w2 = __ldg(&W[(f4 * 4 + 2) * FOUT + o]);
        const float w3 = __ldg(&W[(f4 * 4 + 3) * FOUT + o]);
#pragma unroll
        for (int rr = 0; rr < 8; ++rr) {
            const float4 hv = *(const float4*)&sh_h[(g * 8 + rr) * FIN + f4 * 4];
            acc[rr] = fmaf(hv.x, w0, acc[rr]);
            acc[rr] = fmaf(hv.y, w1, acc[rr]);
            acc[rr] = fmaf(hv.z, w2, acc[rr]);
            acc[rr] = fmaf(hv.w, w3, acc[rr]);
        }
    }

    const int lane = t & 31;
    const int half = (t >> 5) & 1;
#pragma unroll
    for (int rr = 0; rr < 8; ++rr) {
        const int row = row0 + g * 8 + rr;
        const float lev = __ldg(&level[row]);
        g_WhL[(size_t)row * FOUT + o] = acc[rr] * lev;
        float v1 = acc[rr] * a1o;
        float v2 = acc[rr] * a2o;
#pragma unroll
        for (int off = 16; off; off >>= 1) {
            v1 += __shfl_down_sync(0xffffffffu, v1, off);
            v2 += __shfl_down_sync(0xffffffffu, v2, off);
        }
        if (lane == 0) { red1[rr][g][half] = v1; red2[rr][g][half] = v2; }
    }
    __syncthreads();
    if (t < 32) {
        const int g2 = t >> 3, rr2 = t & 7;
        const int row = row0 + g2 * 8 + rr2;
        g_f1[row] = red1[rr2][g2][0] + red1[rr2][g2][1];
        g_f2[row] = red2[rr2][g2][0] + red2[rr2][g2][1];
    }
}

// =====================================================================
// Kernel B: compute exp(e-16) (0 where masked), store to g_expe, and
// accumulate partial column sums. Thread owns column j -> coalesced.
// =====================================================================
__global__ __launch_bounds__(256) void k_colsum(const int* __restrict__ adj,
                                                const float* __restrict__ nt)
{
    const int j = blockIdx.x * 256 + threadIdx.x;
    const int b = blockIdx.y;
    const int i0 = blockIdx.z * (NN / SPLIT);

    const float f2j = __ldg(&g_f2[b * NN + j]);
    const float* f1p = g_f1 + b * NN + i0;
    size_t base = ((size_t)(b * NN + i0)) * NN + j;

    float s = 0.f;
#pragma unroll 4
    for (int ii = 0; ii < NN / SPLIT; ++ii) {
        const int av = __ldg(adj + base);
        const float ntv = __ldg(nt + base);
        const float f1i = __ldg(&f1p[ii]);
        float pv = 0.f;
        if (av > 0) {
            const float x = f1i + f2j;
            const float e = (x > 0.f ? x : LALPHA * x) * ntv;
            pv = __expf(e - EBIAS);
            s += pv;
        }
        g_expe[base] = pv;
        base += NN;
    }
    g_part[((size_t)blockIdx.z * BB + b) * NN + j] = s;
}

// =====================================================================
// Combine partials -> 1/colsum
// =====================================================================
__global__ __launch_bounds__(256) void k_comb()
{
    const int c = blockIdx.x * 256 + threadIdx.x;
    float s = 0.f;
#pragma unroll
    for (int k = 0; k < SPLIT; ++k) s += g_part[k * (BB * NN) + c];
    g_inv[c] = 1.0f / s;
}

// =====================================================================
// Scale WhL by inv (fold softmax denominator into the V operand)
// =====================================================================
__global__ __launch_bounds__(256) void k_scale()
{
    const int i4 = blockIdx.x * 256 + threadIdx.x;      // float4 index
    const float inv = g_inv[i4 >> 4];                   // 16 float4 per column
    float4 v = ((float4*)g_WhL)[i4];
    v.x *= inv; v.y *= inv; v.z *= inv; v.w *= inv;
    ((float4*)g_WhL)[i4] = v;
}

// =====================================================================
// Kernel C: partial h_prime over a j-slice.
// grid (32 i-tiles, B, SPLITJ); 64 i x 64 o per block, FFMA2 inner loop.
// =====================================================================
__global__ __launch_bounds__(256) void k_attn()
{
    __shared__ float sh_w[64 * 64];   // scaled WhL chunk [jj][o]
    __shared__ float sh_p[64 * 65];   // P transposed [jj][il], padded

    const int t = threadIdx.x;
    const int i0 = blockIdx.x * 64;
    const int b  = blockIdx.y;
    const int js = blockIdx.z;

    const int jj = t & 63;
    const int ig = t >> 6;            // 4 groups x 16 rows
    const int il = t & 31;
    const int oc = (t >> 5) * 8;

    unsigned long long acc0[4] = {0ull, 0ull, 0ull, 0ull};
    unsigned long long acc1[4] = {0ull, 0ull, 0ull, 0ull};

    for (int jt = 0; jt < NN / SPLITJ / 64; ++jt) {
        const int j0 = js * (NN / SPLITJ) + jt * 64;

        // --- stage scaled WhL chunk (contiguous float4) ---
        {
            const float4* src = (const float4*)(g_WhL + ((size_t)(b * NN + j0)) * FOUT);
            float4* dst = (float4*)sh_w;
#pragma unroll
            for (int k = 0; k < 4; ++k) dst[t + k * 256] = src[t + k * 256];
        }

        // --- stage P tile transposed (pure copy, coalesced LDG, cf STS) ---
        {
            const float* ep = g_expe + ((size_t)(b * NN + i0 + ig * 16)) * NN + j0 + jj;
#pragma unroll
            for (int r = 0; r < 16; ++r)
                sh_p[jj * 65 + ig * 16 + r] = __ldg(ep + (size_t)r * NN);
        }
        __syncthreads();

        // --- acc[i][o] += P[i][j] * WhL'[j][o]  (packed f32x2) ---
#pragma unroll 8
        for (int j = 0; j < 64; ++j) {
            const float p0 = sh_p[j * 65 + il];
            const float p1 = sh_p[j * 65 + il + 32];
            unsigned long long pp0, pp1;
            asm("mov.b64 %0, {%1, %1};" : "=l"(pp0) : "f"(p0));
            asm("mov.b64 %0, {%1, %1};" : "=l"(pp1) : "f"(p1));
            const ulonglong2* wv = (const ulonglong2*)&sh_w[j * 64 + oc];
            const ulonglong2 wA = wv[0];
            const ulonglong2 wB = wv[1];
            asm("fma.rn.f32x2 %0, %1, %2, %0;" : "+l"(acc0[0]) : "l"(pp0), "l"(wA.x));
            asm("fma.rn.f32x2 %0, %1, %2, %0;" : "+l"(acc0[1]) : "l"(pp0), "l"(wA.y));
            asm("fma.rn.f32x2 %0, %1, %2, %0;" : "+l"(acc0[2]) : "l"(pp0), "l"(wB.x));
            asm("fma.rn.f32x2 %0, %1, %2, %0;" : "+l"(acc0[3]) : "l"(pp0), "l"(wB.y));
            asm("fma.rn.f32x2 %0, %1, %2, %0;" : "+l"(acc1[0]) : "l"(pp1), "l"(wA.x));
            asm("fma.rn.f32x2 %0, %1, %2, %0;" : "+l"(acc1[1]) : "l"(pp1), "l"(wA.y));
            asm("fma.rn.f32x2 %0, %1, %2, %0;" : "+l"(acc1[2]) : "l"(pp1), "l"(wB.x));
            asm("fma.rn.f32x2 %0, %1, %2, %0;" : "+l"(acc1[3]) : "l"(pp1), "l"(wB.y));
        }
        __syncthreads();
    }

    // --- store partials (no relu yet) ---
    float r0[8], r1[8];
#pragma unroll
    for (int k = 0; k < 4; ++k) {
        asm("mov.b64 {%0, %1}, %2;" : "=f"(r0[2*k]), "=f"(r0[2*k+1]) : "l"(acc0[k]));
        asm("mov.b64 {%0, %1}, %2;" : "=f"(r1[2*k]), "=f"(r1[2*k+1]) : "l"(acc1[k]));
    }
    float* op0 = g_pout + (((size_t)js * BB + b) * NN + i0 + il) * FOUT + oc;
    float* op1 = op0 + (size_t)32 * FOUT;
    ((float4*)op0)[0] = make_float4(r0[0], r0[1], r0[2], r0[3]);
    ((float4*)op0)[1] = make_float4(r0[4], r0[5], r0[6], r0[7]);
    ((float4*)op1)[0] = make_float4(r1[0], r1[1], r1[2], r1[3]);
    ((float4*)op1)[1] = make_float4(r1[4], r1[5], r1[6], r1[7]);
}

// =====================================================================
// Combine j-split partials + relu -> out
// =====================================================================
__global__ __launch_bounds__(256) void k_out(float* __restrict__ out)
{
    const int i4 = blockIdx.x * 256 + threadIdx.x;   // float4 index
    const size_t stride4 = (size_t)BB * NN * FOUT / 4;
    float4 s = ((const float4*)g_pout)[i4];
#pragma unroll
    for (int k = 1; k < SPLITJ; ++k) {
        const float4 v = ((const float4*)g_pout)[k * stride4 + i4];
        s.x += v.x; s.y += v.y; s.z += v.z; s.w += v.w;
    }
    s.x = fmaxf(s.x, 0.f); s.y = fmaxf(s.y, 0.f);
    s.z = fmaxf(s.z, 0.f); s.w = fmaxf(s.w, 0.f);
    ((float4*)out)[i4] = s;
}

// =====================================================================
extern "C" void kernel_launch(void* const* d_in, const int* in_sizes, int n_in,
                              void* d_out, int out_size)
{
    const float* h     = (const float*)d_in[0];
    const int*   adj   = (const int*)  d_in[1];
    const float* level = (const float*)d_in[2];
    const float* nt    = (const float*)d_in[3];
    const float* W     = (const float*)d_in[4];
    const float* a     = (const float*)d_in[5];
    float* out = (float*)d_out;

    k_proj<<<(BB * NN) / 32, 256>>>(h, W, a, level);
    dim3 gb(NN / 256, BB, SPLIT);
    k_colsum<<<gb, 256>>>(adj, nt);
    k_comb<<<(BB * NN) / 256, 256>>>();
    k_scale<<<(BB * NN * FOUT / 4) / 256, 256>>>();
    dim3 ga(NN / 64, BB, SPLITJ);
    k_attn<<<ga, 256>>>();
    k_out<<<(BB * NN * FOUT / 4) / 256, 256>>>(out);
}